// round 5
// baseline (speedup 1.0000x reference)
#include <cuda_runtime.h>

// RMAC max-pooling, x: (64, 37, 37, 512) f32 NHWC -> out: (64, 14, 512) f32.
// 14 static regions = products of 6 x-intervals and 6 y-intervals:
//   x/y-int: 0:[0,37) 1:[0,24) 2:[13,37) 3:[0,18) 4:[9,27) 5:[19,37)
//
// R5 = R4 resubmit (R4 bench was an infra failure; kernel never ran).
// Fused structure from R3 (per-band blocks fold rows directly into 14
// per-region register accumulators) with loads restored to float4 (LDG.128):
// 64-thread blocks x float4 = 256 channels, grid (8, 64, 2) = 1024 blocks.

#define NEG_INF __int_as_float(0xff800000)

#define NBANDS 8
// Partial region maxes: [64][8 bands][14 regions][512 ch] f32 = 14.7 MB.
__device__ float g_P[64 * NBANDS * 14 * 512];

__constant__ int c_b0[NBANDS] = {0, 5, 10, 15, 20, 25, 29, 33};
__constant__ int c_b1[NBANDS] = {5, 10, 15, 20, 25, 29, 33, 37};

__device__ __forceinline__ float4 fmax4(float4 a, float4 b) {
    return make_float4(fmaxf(a.x, b.x), fmaxf(a.y, b.y),
                       fmaxf(a.z, b.z), fmaxf(a.w, b.w));
}

// K1: grid (8, 64, 2); 64 threads x float4 = 256 channels per block.
__global__ __launch_bounds__(64) void rmac_k1(const float* __restrict__ x) {
    const int band = blockIdx.x;
    const int b    = blockIdx.y;
    const int c4   = blockIdx.z * 64 + threadIdx.x;  // float4 channel idx 0..127

    const float4* __restrict__ x4 = (const float4*)x;

    const float4 ninf = make_float4(NEG_INF, NEG_INF, NEG_INF, NEG_INF);
    float4 acc[14];
#pragma unroll
    for (int r = 0; r < 14; ++r) acc[r] = ninf;

    const int h0 = c_b0[band];
    const int h1 = c_b1[band];

    for (int h = h0; h < h1; ++h) {
        float4 s0 = ninf, s1 = ninf, s2 = ninf, s3 = ninf,
               s4 = ninf, s5 = ninf, s6 = ninf;
        // float4 row base: ((b*37 + h)*37 + w)*128 + c4
        size_t rb = ((size_t)(b * 37 + h) * 37) * 128 + c4;
#pragma unroll
        for (int w = 0; w < 37; ++w) {
            float4 v = x4[rb + (size_t)w * 128];
            if      (w <  9) s0 = fmax4(s0, v);
            else if (w < 13) s1 = fmax4(s1, v);
            else if (w < 18) s2 = fmax4(s2, v);
            else if (w < 19) s3 = fmax4(s3, v);
            else if (w < 24) s4 = fmax4(s4, v);
            else if (w < 27) s5 = fmax4(s5, v);
            else             s6 = fmax4(s6, v);
        }

        // 7 w-segments -> 6 x-interval maxes.
        float4 I3 = fmax4(fmax4(s0, s1), s2);                        // [0,18)
        float4 I1 = fmax4(fmax4(I3, s3), s4);                        // [0,24)
        float4 I5 = fmax4(fmax4(s4, s5), s6);                        // [19,37)
        float4 I0 = fmax4(I1, fmax4(s5, s6));                        // [0,37)
        float4 I2 = fmax4(fmax4(s2, s3), I5);                        // [13,37)
        float4 I4 = fmax4(fmax4(s1, s2), fmax4(s3, fmax4(s4, s5)));  // [9,27)

        // Fold row into region accumulators (uniform predicates on h).
        acc[0] = fmax4(acc[0], I0);                                  // y[0,37)
        if (h < 24)            { acc[1] = fmax4(acc[1], I1);         // y[0,24)
                                 acc[2] = fmax4(acc[2], I2); }
        if (h >= 13)           { acc[3] = fmax4(acc[3], I1);         // y[13,37)
                                 acc[4] = fmax4(acc[4], I2); }
        if (h < 18)            { acc[5] = fmax4(acc[5], I3);         // y[0,18)
                                 acc[6] = fmax4(acc[6], I4);
                                 acc[7] = fmax4(acc[7], I5); }
        if (h >= 9 && h < 27)  { acc[8]  = fmax4(acc[8],  I3);       // y[9,27)
                                 acc[9]  = fmax4(acc[9],  I4);
                                 acc[10] = fmax4(acc[10], I5); }
        if (h >= 19)           { acc[11] = fmax4(acc[11], I3);       // y[19,37)
                                 acc[12] = fmax4(acc[12], I4);
                                 acc[13] = fmax4(acc[13], I5); }
    }

    // Write partials: g_P[b][band][r][512ch], float4 view.
    float4* P4 = (float4*)g_P;
    size_t ob = ((size_t)((b * NBANDS + band) * 14)) * 128 + c4;
#pragma unroll
    for (int r = 0; r < 14; ++r) {
        P4[ob + (size_t)r * 128] = acc[r];
    }
}

// K2: grid (14, 64) x 128 threads, float4; max over 8 band partials.
__global__ __launch_bounds__(128) void rmac_k2(float* __restrict__ out) {
    const int r  = blockIdx.x;
    const int b  = blockIdx.y;
    const int c4 = threadIdx.x;

    const float4* __restrict__ P4 = (const float4*)g_P;
    float4 a = make_float4(NEG_INF, NEG_INF, NEG_INF, NEG_INF);

#pragma unroll
    for (int band = 0; band < NBANDS; ++band) {
        float4 v = P4[((size_t)((b * NBANDS + band) * 14 + r)) * 128 + c4];
        a = fmax4(a, v);
    }

    ((float4*)out)[((size_t)(b * 14 + r)) * 128 + c4] = a;
}

extern "C" void kernel_launch(void* const* d_in, const int* in_sizes, int n_in,
                              void* d_out, int out_size) {
    const float* x = (const float*)d_in[0];
    float* out = (float*)d_out;

    rmac_k1<<<dim3(NBANDS, 64, 2), 64>>>(x);
    rmac_k2<<<dim3(14, 64), 128>>>(out);
}

// round 6
// speedup vs baseline: 1.0899x; 1.0899x over previous
#include <cuda_runtime.h>

// RMAC max-pooling, x: (64, 37, 37, 512) f32 NHWC -> out: (64, 14, 512) f32.
// Regions = products of 6 x-intervals and 6 y-intervals:
//   0:[0,37) 1:[0,24) 2:[13,37) 3:[0,18) 4:[9,27) 5:[19,37)
//   r0:(y0,x0) r1:(y1,x1) r2:(y1,x2) r3:(y2,x1) r4:(y2,x2)
//   r5-7:(y3,x3/4/5) r8-10:(y4,x3/4/5) r11-13:(y5,x3/4/5)
//
// R6: K1 keeps R2's proven-fast per-block profile (7 segment accumulators
// only, ~28 value regs -> deep LDG.128 batching) but blocks cover 17
// sub-bands of 1-3 rows whose boundaries include all y-segment boundaries,
// so each sub-band has a single y-membership. Table: [b][xint][sub][512]
// = 13.4 MB (vs 29 MB in R2). K2 reads each entry exactly once, reducing
// per x-interval over sub-bands into 6 y-accs via compile-time masks.

#define NEG_INF __int_as_float(0xff800000)
#define NSUB 17

// Partial table: [64][6 x-intervals][17 sub-bands][512 ch] = 13.4 MB.
__device__ float g_P[64 * 6 * NSUB * 512];

__constant__ int c_sstart[NSUB] = {0, 2, 4, 7, 9, 11, 13, 15, 18, 19, 20, 22, 24, 27, 29, 32, 34};
__constant__ int c_slen[NSUB]   = {2, 2, 3, 2, 2, 2, 2, 3, 1, 1, 2, 2, 3, 2, 3, 2, 3};

__device__ __forceinline__ float4 fmax4(float4 a, float4 b) {
    return make_float4(fmaxf(a.x, b.x), fmaxf(a.y, b.y),
                       fmaxf(a.z, b.z), fmaxf(a.w, b.w));
}

// K1: grid (17, 64) x 128 threads, float4 = full 512 channels per block.
__global__ __launch_bounds__(128) void rmac_k1(const float* __restrict__ x) {
    const int s  = blockIdx.x;   // sub-band 0..16
    const int b  = blockIdx.y;   // batch
    const int c4 = threadIdx.x;  // float4 channel idx 0..127

    const float4* __restrict__ x4 = (const float4*)x;

    const float4 ninf = make_float4(NEG_INF, NEG_INF, NEG_INF, NEG_INF);
    float4 s0 = ninf, s1 = ninf, s2 = ninf, s3 = ninf,
           s4 = ninf, s5 = ninf, s6 = ninf;

    const int h0  = c_sstart[s];
    const int len = c_slen[s];

    for (int hh = 0; hh < len; ++hh) {
        const int h = h0 + hh;
        size_t rb = ((size_t)(b * 37 + h) * 37) * 128 + c4;
#pragma unroll
        for (int w = 0; w < 37; ++w) {
            float4 v = x4[rb + (size_t)w * 128];
            if      (w <  9) s0 = fmax4(s0, v);
            else if (w < 13) s1 = fmax4(s1, v);
            else if (w < 18) s2 = fmax4(s2, v);
            else if (w < 19) s3 = fmax4(s3, v);
            else if (w < 24) s4 = fmax4(s4, v);
            else if (w < 27) s5 = fmax4(s5, v);
            else             s6 = fmax4(s6, v);
        }
    }

    // 7 w-segments -> 6 x-interval maxes.
    float4 I3 = fmax4(fmax4(s0, s1), s2);                        // [0,18)
    float4 I1 = fmax4(fmax4(I3, s3), s4);                        // [0,24)
    float4 I5 = fmax4(fmax4(s4, s5), s6);                        // [19,37)
    float4 I0 = fmax4(I1, fmax4(s5, s6));                        // [0,37)
    float4 I2 = fmax4(fmax4(s2, s3), I5);                        // [13,37)
    float4 I4 = fmax4(fmax4(s1, s2), fmax4(s3, fmax4(s4, s5)));  // [9,27)

    // Table layout [b][i][s][512] so K2's per-(b,i) reads are contiguous.
    float4* P4 = (float4*)g_P;
    size_t base = ((size_t)(b * 6) * NSUB + s) * 128 + c4;
    P4[base + (size_t)(0 * NSUB) * 128] = I0;
    P4[base + (size_t)(1 * NSUB) * 128] = I1;
    P4[base + (size_t)(2 * NSUB) * 128] = I2;
    P4[base + (size_t)(3 * NSUB) * 128] = I3;
    P4[base + (size_t)(4 * NSUB) * 128] = I4;
    P4[base + (size_t)(5 * NSUB) * 128] = I5;
}

// Sub-band s -> bitmask of y-intervals containing it (bit y set).
// y0 all; y1 s<=11; y2 s>=6; y3 s<=7; y4 4<=s<=12; y5 s>=9.
#define YMASK(s) ((unsigned)(1u \
    | ((s) <= 11 ? 2u : 0u) \
    | ((s) >=  6 ? 4u : 0u) \
    | ((s) <=  7 ? 8u : 0u) \
    | (((s) >= 4 && (s) <= 12) ? 16u : 0u) \
    | ((s) >=  9 ? 32u : 0u)))

// K2: grid (6, 64, 2) x 64 threads, float4 (256 ch per block).
__global__ __launch_bounds__(64) void rmac_k2(float* __restrict__ out) {
    const int i  = blockIdx.x;                      // x-interval 0..5
    const int b  = blockIdx.y;
    const int c4 = blockIdx.z * 64 + threadIdx.x;   // float4 ch idx 0..127

    const float4* __restrict__ P4 = (const float4*)g_P;
    const float4 ninf = make_float4(NEG_INF, NEG_INF, NEG_INF, NEG_INF);
    float4 Y[6];
#pragma unroll
    for (int y = 0; y < 6; ++y) Y[y] = ninf;

    size_t base = ((size_t)(b * 6 + i) * NSUB) * 128 + c4;
#pragma unroll
    for (int s = 0; s < NSUB; ++s) {
        float4 v = P4[base + (size_t)s * 128];
        const unsigned m = YMASK(s);
        if (m & 1u)  Y[0] = fmax4(Y[0], v);
        if (m & 2u)  Y[1] = fmax4(Y[1], v);
        if (m & 4u)  Y[2] = fmax4(Y[2], v);
        if (m & 8u)  Y[3] = fmax4(Y[3], v);
        if (m & 16u) Y[4] = fmax4(Y[4], v);
        if (m & 32u) Y[5] = fmax4(Y[5], v);
    }

    float4* O4 = (float4*)out;
    size_t ob = (size_t)b * 14 * 128 + c4;
    switch (i) {
        case 0: O4[ob +  0 * 128] = Y[0]; break;
        case 1: O4[ob +  1 * 128] = Y[1]; O4[ob +  3 * 128] = Y[2]; break;
        case 2: O4[ob +  2 * 128] = Y[1]; O4[ob +  4 * 128] = Y[2]; break;
        case 3: O4[ob +  5 * 128] = Y[3]; O4[ob +  8 * 128] = Y[4];
                O4[ob + 11 * 128] = Y[5]; break;
        case 4: O4[ob +  6 * 128] = Y[3]; O4[ob +  9 * 128] = Y[4];
                O4[ob + 12 * 128] = Y[5]; break;
        case 5: O4[ob +  7 * 128] = Y[3]; O4[ob + 10 * 128] = Y[4];
                O4[ob + 13 * 128] = Y[5]; break;
    }
}

extern "C" void kernel_launch(void* const* d_in, const int* in_sizes, int n_in,
                              void* d_out, int out_size) {
    const float* x = (const float*)d_in[0];
    float* out = (float*)d_out;

    rmac_k1<<<dim3(NSUB, 64), 128>>>(x);
    rmac_k2<<<dim3(6, 64, 2), 64>>>(out);
}